// round 3
// baseline (speedup 1.0000x reference)
#include <cuda_runtime.h>
#include <cstdint>

// Problem constants
#define BATCH 8
#define SEQ 4096
#define DIM 512
#define M_TOT (BATCH * SEQ)     // 32768 tokens
#define KTOT 3584               // 512 (silu) + 512*6 (bases)
#define NTOT 512
#define GN 10                   // grid knots
#define NBASE 6                 // G + K

// ---------------- scratch (device globals; no allocation allowed) ----------
__device__ float g_A[(size_t)M_TOT * KTOT];   // activations, tf32-in-f32 bits
__device__ float g_W[(size_t)KTOT * NTOT];    // combined weight, tf32 bits

// ---------------- helpers ---------------------------------------------------
__device__ __forceinline__ uint32_t f32_to_tf32(float f) {
    uint32_t r;
    asm("cvt.rna.tf32.f32 %0, %1;" : "=r"(r) : "f"(f));
    return r;
}

__device__ __forceinline__ void cp_async16(void* smem, const void* gmem) {
    uint32_t s = (uint32_t)__cvta_generic_to_shared(smem);
    asm volatile("cp.async.cg.shared.global [%0], [%1], 16;" :: "r"(s), "l"(gmem));
}
#define CP_COMMIT() asm volatile("cp.async.commit_group;")
#define CP_WAIT1()  asm volatile("cp.async.wait_group 1;")

__device__ __forceinline__ void mma_tf32(float* d, const uint32_t* a, const uint32_t* b) {
    asm volatile(
        "mma.sync.aligned.m16n8k8.row.col.f32.tf32.tf32.f32 "
        "{%0,%1,%2,%3}, {%4,%5,%6,%7}, {%8,%9}, {%0,%1,%2,%3};"
        : "+f"(d[0]), "+f"(d[1]), "+f"(d[2]), "+f"(d[3])
        : "r"(a[0]), "r"(a[1]), "r"(a[2]), "r"(a[3]), "r"(b[0]), "r"(b[1]));
}

// ---------------- kernel 1: build combined weight [KTOT, NTOT] --------------
// rows [0,512): base_weight[k, n] (already in-major)
// rows [512, 3584): spline_weight[n, k-512] (transpose; k2 = d*6 + j)
__global__ void build_w_kernel(const float* __restrict__ base_w,
                               const float* __restrict__ spline_w) {
    int idx = blockIdx.x * blockDim.x + threadIdx.x;
    if (idx >= KTOT * NTOT) return;
    int k = idx >> 9;          // / 512
    int n = idx & 511;
    float v = (k < DIM) ? base_w[k * DIM + n]
                        : spline_w[(size_t)n * (KTOT - DIM) + (k - DIM)];
    g_W[idx] = __uint_as_float(f32_to_tf32(v));
}

// ---------------- kernel 2: LN + SiLU + B-spline bases ----------------------
// one CTA (128 threads) per token; thread handles 4 features via float4
__global__ void act_kernel(const float* __restrict__ x,
                           const float* __restrict__ ln_w,
                           const float* __restrict__ ln_b,
                           const float* __restrict__ grid) {
    __shared__ float red[2][4];
    int token = blockIdx.x;
    int tid = threadIdx.x;        // 0..127

    float4 v = reinterpret_cast<const float4*>(x + (size_t)token * DIM)[tid];
    float s  = v.x + v.y + v.z + v.w;
    float ss = v.x * v.x + v.y * v.y + v.z * v.z + v.w * v.w;
    #pragma unroll
    for (int o = 16; o > 0; o >>= 1) {
        s  += __shfl_xor_sync(0xffffffffu, s, o);
        ss += __shfl_xor_sync(0xffffffffu, ss, o);
    }
    int warp = tid >> 5, lane = tid & 31;
    if (lane == 0) { red[0][warp] = s; red[1][warp] = ss; }
    __syncthreads();
    s  = red[0][0] + red[0][1] + red[0][2] + red[0][3];
    ss = red[1][0] + red[1][1] + red[1][2] + red[1][3];
    float mean = s * (1.0f / DIM);
    float var  = ss * (1.0f / DIM) - mean * mean;
    float rstd = rsqrtf(var + 1e-5f);

    float* arow = g_A + (size_t)token * KTOT;
    float xs[4] = {v.x, v.y, v.z, v.w};

    #pragma unroll
    for (int j = 0; j < 4; j++) {
        int d = tid * 4 + j;
        float xn = (xs[j] - mean) * rstd * ln_w[d] + ln_b[d];
        float sl = xn / (1.0f + expf(-xn));
        arow[d] = __uint_as_float(f32_to_tf32(sl));

        const float* gp = grid + d * GN;
        float gg[GN];
        #pragma unroll
        for (int i = 0; i < GN; i++) gg[i] = gp[i];

        float b[GN - 1];
        #pragma unroll
        for (int i = 0; i < GN - 1; i++)
            b[i] = (xn >= gg[i] && xn < gg[i + 1]) ? 1.0f : 0.0f;

        #pragma unroll
        for (int k = 1; k <= 3; k++) {
            #pragma unroll
            for (int i = 0; i < GN - 1 - k; i++) {
                float left  = (xn - gg[i]) / (gg[i + k] - gg[i]);
                float right = (gg[i + k + 1] - xn) / (gg[i + k + 1] - gg[i + 1]);
                b[i] = left * b[i] + right * b[i + 1];
            }
        }
        #pragma unroll
        for (int i = 0; i < NBASE; i++)
            arow[DIM + d * NBASE + i] = __uint_as_float(f32_to_tf32(b[i]));
    }
}

// ---------------- kernel 3: tf32 GEMM [M_TOT,KTOT] x [KTOT,NTOT] ------------
#define BM 128
#define BN 128
#define BK 16
#define ASTR 20     // padded k-stride of A in smem (conflict-free frag loads)
#define BSTR 132    // padded n-stride of B in smem

__global__ __launch_bounds__(256, 2) void gemm_kernel(float* __restrict__ out,
                                                      const float* __restrict__ bias) {
    __shared__ float As[2][BM * ASTR];
    __shared__ float Bs[2][BK * BSTR];

    // grid.x = N tiles (4) fastest, grid.y = M tiles (256): A-tile reuse in L2
    int n0 = blockIdx.x * BN;
    int m0 = blockIdx.y * BM;
    int tid = threadIdx.x;
    int lane = tid & 31, warp = tid >> 5;
    int wm = warp >> 2;      // 0..1 -> rows [wm*64, +64)
    int wn = warp & 3;       // 0..3 -> cols [wn*32, +32)
    int lr = lane >> 2, lc = lane & 3;

    float acc[4][4][4];
    #pragma unroll
    for (int i = 0; i < 4; i++)
        #pragma unroll
        for (int j = 0; j < 4; j++)
            #pragma unroll
            for (int r = 0; r < 4; r++) acc[i][j][r] = 0.0f;

    const float* gA = g_A + (size_t)m0 * KTOT;
    const float* gW = g_W + n0;

    int am  = tid >> 2;          // 0..63 (row within half-tile)
    int ak4 = (tid & 3) << 2;    // 0,4,8,12
    int bk  = tid >> 5;          // 0..7
    int bn4 = lane << 2;         // 0..124

    const int NK = KTOT / BK;    // 224

    // tile loader
    auto load_tile = [&](int kt, int stg) {
        #pragma unroll
        for (int i = 0; i < 2; i++) {
            int m = am + i * 64;
            cp_async16(&As[stg][m * ASTR + ak4], gA + (size_t)m * KTOT + kt + ak4);
        }
        #pragma unroll
        for (int i = 0; i < 2; i++) {
            int k = bk + i * 8;
            cp_async16(&Bs[stg][k * BSTR + bn4], gW + (size_t)(kt + k) * NTOT + bn4);
        }
    };

    load_tile(0, 0);
    CP_COMMIT();

    for (int t = 0; t < NK; t++) {
        if (t + 1 < NK) load_tile((t + 1) * BK, (t + 1) & 1);
        CP_COMMIT();
        CP_WAIT1();
        __syncthreads();

        int stg = t & 1;
        #pragma unroll
        for (int kk = 0; kk < 2; kk++) {
            int k0 = kk * 8;
            uint32_t af[4][4];
            #pragma unroll
            for (int mt = 0; mt < 4; mt++) {
                int row = wm * 64 + mt * 16 + lr;
                af[mt][0] = __float_as_uint(As[stg][row * ASTR + k0 + lc]);
                af[mt][1] = __float_as_uint(As[stg][(row + 8) * ASTR + k0 + lc]);
                af[mt][2] = __float_as_uint(As[stg][row * ASTR + k0 + lc + 4]);
                af[mt][3] = __float_as_uint(As[stg][(row + 8) * ASTR + k0 + lc + 4]);
            }
            uint32_t bf[4][2];
            #pragma unroll
            for (int nt = 0; nt < 4; nt++) {
                int col = wn * 32 + nt * 8 + lr;
                bf[nt][0] = __float_as_uint(Bs[stg][(k0 + lc) * BSTR + col]);
                bf[nt][1] = __float_as_uint(Bs[stg][(k0 + lc + 4) * BSTR + col]);
            }
            #pragma unroll
            for (int mt = 0; mt < 4; mt++)
                #pragma unroll
                for (int nt = 0; nt < 4; nt++)
                    mma_tf32(acc[mt][nt], af[mt], bf[nt]);
        }
        __syncthreads();
    }

    // epilogue: + bias, write fp32 output
    #pragma unroll
    for (int mt = 0; mt < 4; mt++) {
        #pragma unroll
        for (int nt = 0; nt < 4; nt++) {
            int row = m0 + wm * 64 + mt * 16 + lr;
            int col = n0 + wn * 32 + nt * 8 + lc * 2;
            float b0 = __ldg(bias + col), b1 = __ldg(bias + col + 1);
            float2 v0 = make_float2(acc[mt][nt][0] + b0, acc[mt][nt][1] + b1);
            float2 v1 = make_float2(acc[mt][nt][2] + b0, acc[mt][nt][3] + b1);
            *reinterpret_cast<float2*>(out + (size_t)row * NTOT + col) = v0;
            *reinterpret_cast<float2*>(out + (size_t)(row + 8) * NTOT + col) = v1;
        }
    }
}

// ---------------- launch -----------------------------------------------------
extern "C" void kernel_launch(void* const* d_in, const int* in_sizes, int n_in,
                              void* d_out, int out_size) {
    const float* x        = (const float*)d_in[0];
    const float* ln_w     = (const float*)d_in[1];
    const float* ln_b     = (const float*)d_in[2];
    const float* base_w   = (const float*)d_in[3];
    const float* base_b   = (const float*)d_in[4];
    const float* spline_w = (const float*)d_in[5];
    const float* grid     = (const float*)d_in[6];
    float* out = (float*)d_out;

    build_w_kernel<<<(KTOT * NTOT + 255) / 256, 256>>>(base_w, spline_w);
    act_kernel<<<M_TOT, 128>>>(x, ln_w, ln_b, grid);
    dim3 g(NTOT / BN, M_TOT / BM);   // N fastest -> A-tile L2 reuse
    gemm_kernel<<<g, 256>>>(out, base_b);
}

// round 5
// speedup vs baseline: 1.0836x; 1.0836x over previous
#include <cuda_runtime.h>
#include <cstdint>

#define BATCH 8
#define SEQ 4096
#define DIM 512
#define M_TOT (BATCH * SEQ)     // 32768
#define KTOT 3584               // 512 + 512*6
#define NTOT 512
#define GN 10
#define NBASE 6

// GEMM tiling
#define BM 128
#define BN 256
#define BK 32
#define STAGES 3
#define NSTG (KTOT / BK)        // 112
#define ASTR 36                 // padded A k-stride (floats)
#define BSTR 264                // padded B n-stride (floats)
#define A_FLOATS (BM * ASTR)    // 4608
#define B_FLOATS (BK * BSTR)    // 8448
#define SM_B_OFF (STAGES * A_FLOATS)          // 13824
#define SMEM_FLOATS (SM_B_OFF + STAGES * B_FLOATS)
#define SMEM_BYTES (SMEM_FLOATS * 4)          // 156672

// ---------------- scratch ----------------------------------------------------
__device__ float g_A[(size_t)M_TOT * KTOT];   // activations [M, K], tf32 bits
__device__ float g_W[(size_t)KTOT * NTOT];    // combined weight [K, N], tf32 bits

// ---------------- helpers ---------------------------------------------------
__device__ __forceinline__ uint32_t f32_to_tf32(float f) {
    uint32_t r; asm("cvt.rna.tf32.f32 %0, %1;" : "=r"(r) : "f"(f)); return r;
}
__device__ __forceinline__ void cp_async16(void* smem, const void* gmem) {
    uint32_t s = (uint32_t)__cvta_generic_to_shared(smem);
    asm volatile("cp.async.cg.shared.global [%0], [%1], 16;" :: "r"(s), "l"(gmem));
}
#define CP_COMMIT() asm volatile("cp.async.commit_group;")
#define CP_WAIT1()  asm volatile("cp.async.wait_group 1;")   // STAGES-2

__device__ __forceinline__ void mma_tf32(float* d, const uint32_t* a, const uint32_t* b) {
    asm volatile(
        "mma.sync.aligned.m16n8k8.row.col.f32.tf32.tf32.f32 "
        "{%0,%1,%2,%3}, {%4,%5,%6,%7}, {%8,%9}, {%0,%1,%2,%3};"
        : "+f"(d[0]), "+f"(d[1]), "+f"(d[2]), "+f"(d[3])
        : "r"(a[0]), "r"(a[1]), "r"(a[2]), "r"(a[3]), "r"(b[0]), "r"(b[1]));
}

// ---------------- kernel 1: build combined weight [K, N] --------------------
// k in [0,512): base_weight[k, n];  k >= 512: spline_weight[n, k-512]
__global__ void build_w_kernel(const float* __restrict__ base_w,
                               const float* __restrict__ spline_w) {
    int idx = blockIdx.x * blockDim.x + threadIdx.x;
    if (idx >= KTOT * NTOT) return;
    int k = idx >> 9, n = idx & 511;
    float v = (k < DIM) ? base_w[k * DIM + n]
                        : spline_w[(size_t)n * (KTOT - DIM) + (k - DIM)];
    g_W[idx] = __uint_as_float(f32_to_tf32(v));
}

// ---------------- kernel 2: LN + SiLU + B-splines -> g_A --------------------
__global__ void act_kernel(const float* __restrict__ x,
                           const float* __restrict__ ln_w,
                           const float* __restrict__ ln_b,
                           const float* __restrict__ grid) {
    __shared__ float red[2][4];
    int token = blockIdx.x;
    int tid = threadIdx.x;        // 0..127

    float4 v = reinterpret_cast<const float4*>(x + (size_t)token * DIM)[tid];
    float s  = v.x + v.y + v.z + v.w;
    float ss = v.x * v.x + v.y * v.y + v.z * v.z + v.w * v.w;
    #pragma unroll
    for (int o = 16; o > 0; o >>= 1) {
        s  += __shfl_xor_sync(0xffffffffu, s, o);
        ss += __shfl_xor_sync(0xffffffffu, ss, o);
    }
    int warp = tid >> 5, lane = tid & 31;
    if (lane == 0) { red[0][warp] = s; red[1][warp] = ss; }
    __syncthreads();
    s  = red[0][0] + red[0][1] + red[0][2] + red[0][3];
    ss = red[1][0] + red[1][1] + red[1][2] + red[1][3];
    float mean = s * (1.0f / DIM);
    float var  = ss * (1.0f / DIM) - mean * mean;
    float rstd = rsqrtf(var + 1e-5f);

    float* arow = g_A + (size_t)token * KTOT;
    float xs[4] = {v.x, v.y, v.z, v.w};

    #pragma unroll
    for (int j = 0; j < 4; j++) {
        int d = tid * 4 + j;
        float xn = (xs[j] - mean) * rstd * ln_w[d] + ln_b[d];
        float sl = xn / (1.0f + expf(-xn));
        arow[d] = __uint_as_float(f32_to_tf32(sl));

        const float* gp = grid + d * GN;
        float gg[GN];
        #pragma unroll
        for (int i = 0; i < GN; i++) gg[i] = gp[i];
        float b[GN - 1];
        #pragma unroll
        for (int i = 0; i < GN - 1; i++)
            b[i] = (xn >= gg[i] && xn < gg[i + 1]) ? 1.0f : 0.0f;
        #pragma unroll
        for (int k = 1; k <= 3; k++) {
            #pragma unroll
            for (int i = 0; i < GN - 1 - k; i++) {
                float left  = (xn - gg[i]) / (gg[i + k] - gg[i]);
                float right = (gg[i + k + 1] - xn) / (gg[i + k + 1] - gg[i + 1]);
                b[i] = left * b[i] + right * b[i + 1];
            }
        }
        #pragma unroll
        for (int i = 0; i < NBASE; i++)
            arow[DIM + d * NBASE + i] = __uint_as_float(f32_to_tf32(b[i]));
    }
}

// ---------------- kernel 3: tf32 mma.sync GEMM 128x256, 3-stage -------------
__device__ __forceinline__ void load_stage(float* sm, int stg, const float* gA,
                                           int n0, int kt, int tid) {
    float* As = sm + stg * A_FLOATS;
    float* Bs = sm + SM_B_OFF + stg * B_FLOATS;
    // A: 128 rows x 32 k = 1024 x 16B chunks, 4 per thread
    #pragma unroll
    for (int i = 0; i < 4; i++) {
        int id = tid + i * 256;
        int r = id >> 3, c = id & 7;
        cp_async16(As + r * ASTR + c * 4, gA + (size_t)r * KTOT + kt + c * 4);
    }
    // B: 32 k-rows x 256 n = 2048 x 16B chunks, 8 per thread
    #pragma unroll
    for (int i = 0; i < 8; i++) {
        int id = tid + i * 256;
        int r = id >> 6, c = id & 63;
        cp_async16(Bs + r * BSTR + c * 4, g_W + (size_t)(kt + r) * NTOT + n0 + c * 4);
    }
    CP_COMMIT();
}

__global__ void __launch_bounds__(256, 1) gemm_kernel(float* __restrict__ out,
                                                      const float* __restrict__ bias) {
    extern __shared__ float sm[];
    int tid = threadIdx.x;
    int lane = tid & 31, warp = tid >> 5;
    int wm = warp >> 2;           // 0..1 -> M rows [wm*64, +64)
    int wn = warp & 3;            // 0..3 -> N cols [wn*64, +64)
    int lr = lane >> 2, lc = lane & 3;

    int n0 = blockIdx.x * BN;     // x fastest (2 tiles) -> W reuse in L2
    int m0 = blockIdx.y * BM;
    const float* gA = g_A + (size_t)m0 * KTOT;

    float acc[4][8][4];
    #pragma unroll
    for (int i = 0; i < 4; i++)
        #pragma unroll
        for (int j = 0; j < 8; j++)
            #pragma unroll
            for (int r = 0; r < 4; r++) acc[i][j][r] = 0.0f;

    load_stage(sm, 0, gA, n0, 0, tid);
    load_stage(sm, 1, gA, n0, BK, tid);

    for (int t = 0; t < NSTG; t++) {
        CP_WAIT1();                     // stage t resident
        __syncthreads();                // all warps done with stage (t-1)%3 -> safe to refill

        if (t + STAGES - 1 < NSTG)
            load_stage(sm, (t + STAGES - 1) % STAGES, gA, n0, (t + STAGES - 1) * BK, tid);
        else
            CP_COMMIT();                // keep group accounting valid

        int stg = t % STAGES;
        const float* As = sm + stg * A_FLOATS;
        const float* Bs = sm + SM_B_OFF + stg * B_FLOATS;

        #pragma unroll
        for (int kk = 0; kk < 4; kk++) {
            int k0 = kk * 8;
            uint32_t af[4][4];
            #pragma unroll
            for (int mt = 0; mt < 4; mt++) {
                int row = wm * 64 + mt * 16 + lr;
                af[mt][0] = __float_as_uint(As[row * ASTR + k0 + lc]);
                af[mt][1] = __float_as_uint(As[(row + 8) * ASTR + k0 + lc]);
                af[mt][2] = __float_as_uint(As[row * ASTR + k0 + lc + 4]);
                af[mt][3] = __float_as_uint(As[(row + 8) * ASTR + k0 + lc + 4]);
            }
            uint32_t bf[8][2];
            #pragma unroll
            for (int nt = 0; nt < 8; nt++) {
                int col = wn * 64 + nt * 8 + lr;
                bf[nt][0] = __float_as_uint(Bs[(k0 + lc) * BSTR + col]);
                bf[nt][1] = __float_as_uint(Bs[(k0 + lc + 4) * BSTR + col]);
            }
            #pragma unroll
            for (int mt = 0; mt < 4; mt++)
                #pragma unroll
                for (int nt = 0; nt < 8; nt++)
                    mma_tf32(acc[mt][nt], af[mt], bf[nt]);
        }
    }

    // epilogue: + bias -> out
    #pragma unroll
    for (int mt = 0; mt < 4; mt++) {
        #pragma unroll
        for (int nt = 0; nt < 8; nt++) {
            int row = m0 + wm * 64 + mt * 16 + lr;
            int col = n0 + wn * 64 + nt * 8 + lc * 2;
            float b0 = __ldg(bias + col), b1 = __ldg(bias + col + 1);
            float2 v0 = make_float2(acc[mt][nt][0] + b0, acc[mt][nt][1] + b1);
            float2 v1 = make_float2(acc[mt][nt][2] + b0, acc[mt][nt][3] + b1);
            *reinterpret_cast<float2*>(out + (size_t)row * NTOT + col) = v0;
            *reinterpret_cast<float2*>(out + (size_t)(row + 8) * NTOT + col) = v1;
        }
    }
}

// ---------------- launch -----------------------------------------------------
extern "C" void kernel_launch(void* const* d_in, const int* in_sizes, int n_in,
                              void* d_out, int out_size) {
    const float* x        = (const float*)d_in[0];
    const float* ln_w     = (const float*)d_in[1];
    const float* ln_b     = (const float*)d_in[2];
    const float* base_w   = (const float*)d_in[3];
    const float* base_b   = (const float*)d_in[4];
    const float* spline_w = (const float*)d_in[5];
    const float* grid     = (const float*)d_in[6];
    float* out = (float*)d_out;

    cudaFuncSetAttribute(gemm_kernel, cudaFuncAttributeMaxDynamicSharedMemorySize, SMEM_BYTES);

    build_w_kernel<<<(KTOT * NTOT + 255) / 256, 256>>>(base_w, spline_w);
    act_kernel<<<M_TOT, 128>>>(x, ln_w, ln_b, grid);
    dim3 g(NTOT / BN, M_TOT / BM);    // (2, 256)
    gemm_kernel<<<g, 256, SMEM_BYTES>>>(out, base_b);
}

// round 6
// speedup vs baseline: 1.3744x; 1.2684x over previous
#include <cuda_runtime.h>
#include <cuda_fp16.h>
#include <cstdint>

#define BATCH 8
#define SEQ 4096
#define DIM 512
#define M_TOT (BATCH * SEQ)     // 32768
#define KTOT 3584               // 512 + 512*6
#define NTOT 512
#define GN 10
#define NBASE 6

// GEMM tiling
#define BM 128
#define BN 256
#define BK 64
#define STAGES 3
#define NSTG (KTOT / BK)        // 56
#define ASTR 72                 // padded A k-stride (halfs)
#define BSTR 72                 // padded B k-stride (halfs), B stored [n][k]
#define A_HALFS (BM * ASTR)     // 9216
#define B_HALFS (BN * BSTR)     // 18432
#define SM_B_OFF (STAGES * A_HALFS)
#define SMEM_BYTES ((SM_B_OFF + STAGES * B_HALFS) * 2)   // 165888

// ---------------- scratch ----------------------------------------------------
__device__ __half g_A[(size_t)M_TOT * KTOT];   // activations [M, K]
__device__ __half g_W[(size_t)NTOT * KTOT];    // weight^T [N, K]

// ---------------- helpers ---------------------------------------------------
__device__ __forceinline__ void cp_async16(void* smem, const void* gmem) {
    uint32_t s = (uint32_t)__cvta_generic_to_shared(smem);
    asm volatile("cp.async.cg.shared.global [%0], [%1], 16;" :: "r"(s), "l"(gmem));
}
#define CP_COMMIT() asm volatile("cp.async.commit_group;")
#define CP_WAIT1()  asm volatile("cp.async.wait_group 1;")

__device__ __forceinline__ void mma_f16(float* d, const uint32_t* a, const uint32_t* b) {
    asm volatile(
        "mma.sync.aligned.m16n8k16.row.col.f32.f16.f16.f32 "
        "{%0,%1,%2,%3}, {%4,%5,%6,%7}, {%8,%9}, {%0,%1,%2,%3};"
        : "+f"(d[0]), "+f"(d[1]), "+f"(d[2]), "+f"(d[3])
        : "r"(a[0]), "r"(a[1]), "r"(a[2]), "r"(a[3]), "r"(b[0]), "r"(b[1]));
}

// ---------------- kernel 1: build W^T [N, K] in fp16 ------------------------
// k in [0,512): base_weight[k, n]; k >= 512: spline_weight[n, k-512]
__global__ void build_w_kernel(const float* __restrict__ base_w,
                               const float* __restrict__ spline_w) {
    int k = blockIdx.x * 256 + threadIdx.x;   // k fastest -> coalesced spline reads
    int n = blockIdx.y;
    float v = (k < DIM) ? base_w[(size_t)k * NTOT + n]
                        : spline_w[(size_t)n * (KTOT - DIM) + (k - DIM)];
    g_W[(size_t)n * KTOT + k] = __float2half_rn(v);
}

// ---------------- kernel 2: LN + SiLU + B-splines -> g_A (fp16) -------------
__global__ void act_kernel(const float* __restrict__ x,
                           const float* __restrict__ ln_w,
                           const float* __restrict__ ln_b,
                           const float* __restrict__ grid) {
    __shared__ float red[2][4];
    int token = blockIdx.x;
    int tid = threadIdx.x;        // 0..127

    float4 v = reinterpret_cast<const float4*>(x + (size_t)token * DIM)[tid];
    float s  = v.x + v.y + v.z + v.w;
    float ss = v.x * v.x + v.y * v.y + v.z * v.z + v.w * v.w;
    #pragma unroll
    for (int o = 16; o > 0; o >>= 1) {
        s  += __shfl_xor_sync(0xffffffffu, s, o);
        ss += __shfl_xor_sync(0xffffffffu, ss, o);
    }
    int warp = tid >> 5, lane = tid & 31;
    if (lane == 0) { red[0][warp] = s; red[1][warp] = ss; }
    __syncthreads();
    s  = red[0][0] + red[0][1] + red[0][2] + red[0][3];
    ss = red[1][0] + red[1][1] + red[1][2] + red[1][3];
    float mean = s * (1.0f / DIM);
    float var  = ss * (1.0f / DIM) - mean * mean;
    float rstd = rsqrtf(var + 1e-5f);

    __half* arow = g_A + (size_t)token * KTOT;
    float xs[4] = {v.x, v.y, v.z, v.w};

    #pragma unroll
    for (int j = 0; j < 4; j++) {
        int d = tid * 4 + j;
        float xn = (xs[j] - mean) * rstd * ln_w[d] + ln_b[d];
        float sl = xn / (1.0f + expf(-xn));
        arow[d] = __float2half_rn(sl);

        const float* gp = grid + d * GN;
        float gg[GN];
        #pragma unroll
        for (int i = 0; i < GN; i++) gg[i] = gp[i];
        float b[GN - 1];
        #pragma unroll
        for (int i = 0; i < GN - 1; i++)
            b[i] = (xn >= gg[i] && xn < gg[i + 1]) ? 1.0f : 0.0f;
        #pragma unroll
        for (int k = 1; k <= 3; k++) {
            #pragma unroll
            for (int i = 0; i < GN - 1 - k; i++) {
                float left  = (xn - gg[i]) / (gg[i + k] - gg[i]);
                float right = (gg[i + k + 1] - xn) / (gg[i + k + 1] - gg[i + 1]);
                b[i] = left * b[i] + right * b[i + 1];
            }
        }
        #pragma unroll
        for (int i = 0; i < NBASE; i++)
            arow[DIM + d * NBASE + i] = __float2half_rn(b[i]);
    }
}

// ---------------- kernel 3: fp16 mma.sync GEMM 128x256, BK=64, 3-stage ------
__device__ __forceinline__ void load_stage(__half* sm, int stg, const __half* gA,
                                           int n0, int kt, int tid) {
    __half* As = sm + stg * A_HALFS;
    __half* Bs = sm + SM_B_OFF + stg * B_HALFS;
    // A: 128 rows x 64 halfs = 1024 x 16B chunks, 4 per thread
    #pragma unroll
    for (int i = 0; i < 4; i++) {
        int id = tid + i * 256;
        int r = id >> 3, c = id & 7;
        cp_async16(As + r * ASTR + c * 8, gA + (size_t)r * KTOT + kt + c * 8);
    }
    // B: 256 n-rows x 64 halfs = 2048 x 16B chunks, 8 per thread
    #pragma unroll
    for (int i = 0; i < 8; i++) {
        int id = tid + i * 256;
        int r = id >> 3, c = id & 7;
        cp_async16(Bs + r * BSTR + c * 8, g_W + (size_t)(n0 + r) * KTOT + kt + c * 8);
    }
    CP_COMMIT();
}

__global__ void __launch_bounds__(256, 1) gemm_kernel(float* __restrict__ out,
                                                      const float* __restrict__ bias) {
    extern __shared__ __half sm[];
    int tid = threadIdx.x;
    int lane = tid & 31, warp = tid >> 5;
    int wm = warp >> 2;           // 0..1 -> M rows [wm*64, +64)
    int wn = warp & 3;            // 0..3 -> N cols [wn*64, +64)
    int lr = lane >> 2, lc = lane & 3;

    int n0 = blockIdx.x * BN;     // x fastest -> W L2 reuse
    int m0 = blockIdx.y * BM;
    const __half* gA = g_A + (size_t)m0 * KTOT;

    float acc[4][8][4];
    #pragma unroll
    for (int i = 0; i < 4; i++)
        #pragma unroll
        for (int j = 0; j < 8; j++)
            #pragma unroll
            for (int r = 0; r < 4; r++) acc[i][j][r] = 0.0f;

    load_stage(sm, 0, gA, n0, 0, tid);
    load_stage(sm, 1, gA, n0, BK, tid);

    for (int t = 0; t < NSTG; t++) {
        CP_WAIT1();
        __syncthreads();

        if (t + STAGES - 1 < NSTG)
            load_stage(sm, (t + STAGES - 1) % STAGES, gA, n0, (t + STAGES - 1) * BK, tid);
        else
            CP_COMMIT();

        int stg = t % STAGES;
        const __half* As = sm + stg * A_HALFS;
        const __half* Bs = sm + SM_B_OFF + stg * B_HALFS;

        #pragma unroll
        for (int kk = 0; kk < 4; kk++) {          // 4 x k16 per stage
            int k0 = kk * 16;
            uint32_t af[4][4];
            #pragma unroll
            for (int mt = 0; mt < 4; mt++) {
                int row = wm * 64 + mt * 16 + lr;
                const __half* p0 = As + row * ASTR + k0 + 2 * lc;
                const __half* p1 = As + (row + 8) * ASTR + k0 + 2 * lc;
                af[mt][0] = *reinterpret_cast<const uint32_t*>(p0);
                af[mt][1] = *reinterpret_cast<const uint32_t*>(p1);
                af[mt][2] = *reinterpret_cast<const uint32_t*>(p0 + 8);
                af[mt][3] = *reinterpret_cast<const uint32_t*>(p1 + 8);
            }
            uint32_t bf[8][2];
            #pragma unroll
            for (int nt = 0; nt < 8; nt++) {
                int col = wn * 64 + nt * 8 + lr;
                const __half* p = Bs + col * BSTR + k0 + 2 * lc;
                bf[nt][0] = *reinterpret_cast<const uint32_t*>(p);
                bf[nt][1] = *reinterpret_cast<const uint32_t*>(p + 8);
            }
            #pragma unroll
            for (int mt = 0; mt < 4; mt++)
                #pragma unroll
                for (int nt = 0; nt < 8; nt++)
                    mma_f16(acc[mt][nt], af[mt], bf[nt]);
        }
    }

    // epilogue: + bias -> out (same accumulator layout as k8 variant)
    #pragma unroll
    for (int mt = 0; mt < 4; mt++) {
        #pragma unroll
        for (int nt = 0; nt < 8; nt++) {
            int row = m0 + wm * 64 + mt * 16 + lr;
            int col = n0 + wn * 64 + nt * 8 + lc * 2;
            float b0 = __ldg(bias + col), b1 = __ldg(bias + col + 1);
            float2 v0 = make_float2(acc[mt][nt][0] + b0, acc[mt][nt][1] + b1);
            float2 v1 = make_float2(acc[mt][nt][2] + b0, acc[mt][nt][3] + b1);
            *reinterpret_cast<float2*>(out + (size_t)row * NTOT + col) = v0;
            *reinterpret_cast<float2*>(out + (size_t)(row + 8) * NTOT + col) = v1;
        }
    }
}

// ---------------- launch -----------------------------------------------------
extern "C" void kernel_launch(void* const* d_in, const int* in_sizes, int n_in,
                              void* d_out, int out_size) {
    const float* x        = (const float*)d_in[0];
    const float* ln_w     = (const float*)d_in[1];
    const float* ln_b     = (const float*)d_in[2];
    const float* base_w   = (const float*)d_in[3];
    const float* base_b   = (const float*)d_in[4];
    const float* spline_w = (const float*)d_in[5];
    const float* grid     = (const float*)d_in[6];
    float* out = (float*)d_out;

    cudaFuncSetAttribute(gemm_kernel, cudaFuncAttributeMaxDynamicSharedMemorySize, SMEM_BYTES);

    dim3 gw(KTOT / 256, NTOT);
    build_w_kernel<<<gw, 256>>>(base_w, spline_w);
    act_kernel<<<M_TOT, 128>>>(x, ln_w, ln_b, grid);
    dim3 g(NTOT / BN, M_TOT / BM);    // (2, 256)
    gemm_kernel<<<g, 256, SMEM_BYTES>>>(out, base_b);
}

// round 7
// speedup vs baseline: 1.4813x; 1.0778x over previous
#include <cuda_runtime.h>
#include <cuda_fp16.h>
#include <cstdint>

#define BATCH 8
#define SEQ 4096
#define DIM 512
#define M_TOT (BATCH * SEQ)     // 32768
#define KTOT 3584               // 512 + 512*6
#define NTOT 512
#define GN 10
#define NBASE 6

// GEMM tiling
#define BM 128
#define BN 128
#define BK 64
#define STAGES 3
#define NSTG (KTOT / BK)        // 56
#define ASTR 72                 // padded k-stride (halfs), A [m][k]
#define BSTR 72                 // padded k-stride (halfs), B [n][k]
#define A_HALFS (BM * ASTR)     // 9216
#define B_HALFS (BN * BSTR)     // 9216
#define SM_B_OFF (STAGES * A_HALFS)
#define SMEM_BYTES ((SM_B_OFF + STAGES * B_HALFS) * 2)   // 110592

// ---------------- scratch ----------------------------------------------------
__device__ __half g_A[(size_t)M_TOT * KTOT];   // activations [M, K]
__device__ __half g_W[(size_t)NTOT * KTOT];    // weight^T [N, K]

// ---------------- helpers ---------------------------------------------------
__device__ __forceinline__ void cp_async16(void* smem, const void* gmem) {
    uint32_t s = (uint32_t)__cvta_generic_to_shared(smem);
    asm volatile("cp.async.cg.shared.global [%0], [%1], 16;" :: "r"(s), "l"(gmem));
}
#define CP_COMMIT() asm volatile("cp.async.commit_group;")
#define CP_WAIT1()  asm volatile("cp.async.wait_group 1;")

__device__ __forceinline__ void ldsm_x4(uint32_t* r, const __half* p) {
    uint32_t a = (uint32_t)__cvta_generic_to_shared(p);
    asm volatile("ldmatrix.sync.aligned.m8n8.x4.shared.b16 {%0,%1,%2,%3}, [%4];"
                 : "=r"(r[0]), "=r"(r[1]), "=r"(r[2]), "=r"(r[3]) : "r"(a));
}

__device__ __forceinline__ void mma_f16(float* d, const uint32_t* a, const uint32_t* b) {
    asm volatile(
        "mma.sync.aligned.m16n8k16.row.col.f32.f16.f16.f32 "
        "{%0,%1,%2,%3}, {%4,%5,%6,%7}, {%8,%9}, {%0,%1,%2,%3};"
        : "+f"(d[0]), "+f"(d[1]), "+f"(d[2]), "+f"(d[3])
        : "r"(a[0]), "r"(a[1]), "r"(a[2]), "r"(a[3]), "r"(b[0]), "r"(b[1]));
}

// ---------------- kernel 1: build W^T [N, K] in fp16 ------------------------
__global__ void build_w_kernel(const float* __restrict__ base_w,
                               const float* __restrict__ spline_w) {
    int k = blockIdx.x * 256 + threadIdx.x;
    int n = blockIdx.y;
    float v = (k < DIM) ? base_w[(size_t)k * NTOT + n]
                        : spline_w[(size_t)n * (KTOT - DIM) + (k - DIM)];
    g_W[(size_t)n * KTOT + k] = __float2half_rn(v);
}

// ---------------- kernel 2: LN + SiLU + B-splines -> g_A (fp16) -------------
__global__ void act_kernel(const float* __restrict__ x,
                           const float* __restrict__ ln_w,
                           const float* __restrict__ ln_b,
                           const float* __restrict__ grid) {
    __shared__ float red[2][4];
    int token = blockIdx.x;
    int tid = threadIdx.x;

    float4 v = reinterpret_cast<const float4*>(x + (size_t)token * DIM)[tid];
    float s  = v.x + v.y + v.z + v.w;
    float ss = v.x * v.x + v.y * v.y + v.z * v.z + v.w * v.w;
    #pragma unroll
    for (int o = 16; o > 0; o >>= 1) {
        s  += __shfl_xor_sync(0xffffffffu, s, o);
        ss += __shfl_xor_sync(0xffffffffu, ss, o);
    }
    int warp = tid >> 5, lane = tid & 31;
    if (lane == 0) { red[0][warp] = s; red[1][warp] = ss; }
    __syncthreads();
    s  = red[0][0] + red[0][1] + red[0][2] + red[0][3];
    ss = red[1][0] + red[1][1] + red[1][2] + red[1][3];
    float mean = s * (1.0f / DIM);
    float var  = ss * (1.0f / DIM) - mean * mean;
    float rstd = rsqrtf(var + 1e-5f);

    __half* arow = g_A + (size_t)token * KTOT;
    float xs[4] = {v.x, v.y, v.z, v.w};

    #pragma unroll
    for (int j = 0; j < 4; j++) {
        int d = tid * 4 + j;
        float xn = (xs[j] - mean) * rstd * ln_w[d] + ln_b[d];
        float sl = xn / (1.0f + expf(-xn));
        arow[d] = __float2half_rn(sl);

        const float* gp = grid + d * GN;
        float gg[GN];
        #pragma unroll
        for (int i = 0; i < GN; i++) gg[i] = gp[i];
        float b[GN - 1];
        #pragma unroll
        for (int i = 0; i < GN - 1; i++)
            b[i] = (xn >= gg[i] && xn < gg[i + 1]) ? 1.0f : 0.0f;
        #pragma unroll
        for (int k = 1; k <= 3; k++) {
            #pragma unroll
            for (int i = 0; i < GN - 1 - k; i++) {
                float left  = (xn - gg[i]) / (gg[i + k] - gg[i]);
                float right = (gg[i + k + 1] - xn) / (gg[i + k + 1] - gg[i + 1]);
                b[i] = left * b[i] + right * b[i + 1];
            }
        }
        #pragma unroll
        for (int i = 0; i < NBASE; i++)
            arow[DIM + d * NBASE + i] = __float2half_rn(b[i]);
    }
}

// ---------------- kernel 3: fp16 GEMM 128x128, BK=64, 3-stage, 2 CTA/SM -----
__device__ __forceinline__ void load_stage(__half* sm, int stg, const __half* gA,
                                           int n0, int kt, int tid) {
    __half* As = sm + stg * A_HALFS;
    __half* Bs = sm + SM_B_OFF + stg * B_HALFS;
    // A: 128 rows x 64 halfs = 1024 chunks of 16B, 4/thread
    #pragma unroll
    for (int i = 0; i < 4; i++) {
        int id = tid + i * 256;
        int r = id >> 3, c = id & 7;
        cp_async16(As + r * ASTR + c * 8, gA + (size_t)r * KTOT + kt + c * 8);
    }
    // B: 128 n-rows x 64 halfs = 1024 chunks, 4/thread
    #pragma unroll
    for (int i = 0; i < 4; i++) {
        int id = tid + i * 256;
        int r = id >> 3, c = id & 7;
        cp_async16(Bs + r * BSTR + c * 8, g_W + (size_t)(n0 + r) * KTOT + kt + c * 8);
    }
    CP_COMMIT();
}

__global__ void __launch_bounds__(256, 2) gemm_kernel(float* __restrict__ out,
                                                      const float* __restrict__ bias) {
    extern __shared__ __half sm[];
    int tid = threadIdx.x;
    int lane = tid & 31, warp = tid >> 5;
    int wm = warp >> 2;           // 0..1 -> M rows [wm*64, +64)
    int wn = warp & 3;            // 0..3 -> N cols [wn*32, +32)
    int lr = lane >> 2, lc = lane & 3;

    int n0 = blockIdx.x * BN;     // x fastest (4) -> W / A-tile L2 reuse
    int m0 = blockIdx.y * BM;
    const __half* gA = g_A + (size_t)m0 * KTOT;

    // ldmatrix per-lane row/column offsets
    int a_row = (lane & 15);              // + rowbase
    int a_koff = (lane >> 4) << 3;        // 0 or 8
    int b_row = (lane & 7) + ((lane & 16) >> 1);   // + colbase
    int b_koff = lane & 8;                // 0 or 8

    float acc[4][4][4];
    #pragma unroll
    for (int i = 0; i < 4; i++)
        #pragma unroll
        for (int j = 0; j < 4; j++)
            #pragma unroll
            for (int r = 0; r < 4; r++) acc[i][j][r] = 0.0f;

    load_stage(sm, 0, gA, n0, 0, tid);
    load_stage(sm, 1, gA, n0, BK, tid);

    for (int t = 0; t < NSTG; t++) {
        CP_WAIT1();
        __syncthreads();

        if (t + STAGES - 1 < NSTG)
            load_stage(sm, (t + STAGES - 1) % STAGES, gA, n0, (t + STAGES - 1) * BK, tid);
        else
            CP_COMMIT();

        int stg = t % STAGES;
        const __half* As = sm + stg * A_HALFS;
        const __half* Bs = sm + SM_B_OFF + stg * B_HALFS;

        #pragma unroll
        for (int kk = 0; kk < 4; kk++) {          // 4 x k16
            int k0 = kk * 16;
            uint32_t af[4][4];
            #pragma unroll
            for (int mt = 0; mt < 4; mt++) {
                int row = wm * 64 + mt * 16 + a_row;
                ldsm_x4(af[mt], As + row * ASTR + k0 + a_koff);
            }
            uint32_t bf[4][2];
            #pragma unroll
            for (int np = 0; np < 2; np++) {      // each x4 covers 2 nt (16 cols)
                uint32_t r[4];
                int col = wn * 32 + np * 16 + b_row;
                ldsm_x4(r, Bs + col * BSTR + k0 + b_koff);
                bf[np * 2][0] = r[0]; bf[np * 2][1] = r[1];
                bf[np * 2 + 1][0] = r[2]; bf[np * 2 + 1][1] = r[3];
            }
            #pragma unroll
            for (int mt = 0; mt < 4; mt++)
                #pragma unroll
                for (int nt = 0; nt < 4; nt++)
                    mma_f16(acc[mt][nt], af[mt], bf[nt]);
        }
    }

    // epilogue: + bias -> out
    #pragma unroll
    for (int mt = 0; mt < 4; mt++) {
        #pragma unroll
        for (int nt = 0; nt < 4; nt++) {
            int row = m0 + wm * 64 + mt * 16 + lr;
            int col = n0 + wn * 32 + nt * 8 + lc * 2;
            float b0 = __ldg(bias + col), b1 = __ldg(bias + col + 1);
            float2 v0 = make_float2(acc[mt][nt][0] + b0, acc[mt][nt][1] + b1);
            float2 v1 = make_float2(acc[mt][nt][2] + b0, acc[mt][nt][3] + b1);
            *reinterpret_cast<float2*>(out + (size_t)row * NTOT + col) = v0;
            *reinterpret_cast<float2*>(out + (size_t)(row + 8) * NTOT + col) = v1;
        }
    }
}

// ---------------- launch -----------------------------------------------------
extern "C" void kernel_launch(void* const* d_in, const int* in_sizes, int n_in,
                              void* d_out, int out_size) {
    const float* x        = (const float*)d_in[0];
    const float* ln_w     = (const float*)d_in[1];
    const float* ln_b     = (const float*)d_in[2];
    const float* base_w   = (const float*)d_in[3];
    const float* base_b   = (const float*)d_in[4];
    const float* spline_w = (const float*)d_in[5];
    const float* grid     = (const float*)d_in[6];
    float* out = (float*)d_out;

    cudaFuncSetAttribute(gemm_kernel, cudaFuncAttributeMaxDynamicSharedMemorySize, SMEM_BYTES);

    dim3 gw(KTOT / 256, NTOT);
    build_w_kernel<<<gw, 256>>>(base_w, spline_w);
    act_kernel<<<M_TOT, 128>>>(x, ln_w, ln_b, grid);
    dim3 g(NTOT / BN, M_TOT / BM);    // (4, 256)
    gemm_kernel<<<g, 256, SMEM_BYTES>>>(out, base_b);
}

// round 8
// speedup vs baseline: 1.7336x; 1.1703x over previous
#include <cuda_runtime.h>
#include <cuda_fp16.h>
#include <cstdint>

#define BATCH 8
#define SEQ 4096
#define DIM 512
#define M_TOT (BATCH * SEQ)     // 32768
#define KTOT 3584               // 512 + 512*6
#define NTOT 512
#define GN 10
#define NBASE 6

// GEMM tiling
#define BM 128
#define BN 128
#define BK 64
#define STAGES 3
#define NSTG (KTOT / BK)        // 56
#define ASTR 72                 // padded k-stride (halfs), A [m][k]
#define BSTR 72                 // padded k-stride (halfs), B [n][k]
#define A_HALFS (BM * ASTR)     // 9216
#define B_HALFS (BN * BSTR)     // 9216
#define SM_B_OFF (STAGES * A_HALFS)
#define SMEM_BYTES ((SM_B_OFF + STAGES * B_HALFS) * 2)   // 110592

// ---------------- scratch ----------------------------------------------------
__device__ __half g_A[(size_t)M_TOT * KTOT];   // activations [M, K]
__device__ __half g_W[(size_t)NTOT * KTOT];    // weight^T [N, K]

// ---------------- helpers ---------------------------------------------------
__device__ __forceinline__ void cp_async16(void* smem, const void* gmem) {
    uint32_t s = (uint32_t)__cvta_generic_to_shared(smem);
    asm volatile("cp.async.cg.shared.global [%0], [%1], 16;" :: "r"(s), "l"(gmem));
}
#define CP_COMMIT() asm volatile("cp.async.commit_group;")
#define CP_WAIT1()  asm volatile("cp.async.wait_group 1;")

__device__ __forceinline__ void ldsm_x4(uint32_t* r, const __half* p) {
    uint32_t a = (uint32_t)__cvta_generic_to_shared(p);
    asm volatile("ldmatrix.sync.aligned.m8n8.x4.shared.b16 {%0,%1,%2,%3}, [%4];"
                 : "=r"(r[0]), "=r"(r[1]), "=r"(r[2]), "=r"(r[3]) : "r"(a));
}

__device__ __forceinline__ void mma_f16(float* d, const uint32_t* a, const uint32_t* b) {
    asm volatile(
        "mma.sync.aligned.m16n8k16.row.col.f32.f16.f16.f32 "
        "{%0,%1,%2,%3}, {%4,%5,%6,%7}, {%8,%9}, {%0,%1,%2,%3};"
        : "+f"(d[0]), "+f"(d[1]), "+f"(d[2]), "+f"(d[3])
        : "r"(a[0]), "r"(a[1]), "r"(a[2]), "r"(a[3]), "r"(b[0]), "r"(b[1]));
}

// ---------------- kernel 1: build W^T [N, K] in fp16 ------------------------
__global__ void build_w_kernel(const float* __restrict__ base_w,
                               const float* __restrict__ spline_w) {
    int k = blockIdx.x * 256 + threadIdx.x;
    int n = blockIdx.y;
    float v = (k < DIM) ? base_w[(size_t)k * NTOT + n]
                        : spline_w[(size_t)n * (KTOT - DIM) + (k - DIM)];
    g_W[(size_t)n * KTOT + k] = __float2half_rn(v);
}

// ---------------- kernel 2: LN + SiLU + B-splines -> g_A (fp16) -------------
// 64 threads per token, 8 consecutive features per thread.
// All stores are 16-byte STG.128: 1x silu vec + 6x basis vec per thread.
__global__ void __launch_bounds__(64) act_kernel(const float* __restrict__ x,
                                                 const float* __restrict__ ln_w,
                                                 const float* __restrict__ ln_b,
                                                 const float* __restrict__ grid) {
    __shared__ float red[2][2];
    int token = blockIdx.x;
    int tid = threadIdx.x;        // 0..63

    const float4* xr = reinterpret_cast<const float4*>(x + (size_t)token * DIM);
    float4 v0 = xr[tid * 2], v1 = xr[tid * 2 + 1];
    float xs[8] = {v0.x, v0.y, v0.z, v0.w, v1.x, v1.y, v1.z, v1.w};

    float s = 0.f, ss = 0.f;
    #pragma unroll
    for (int i = 0; i < 8; i++) { s += xs[i]; ss += xs[i] * xs[i]; }
    #pragma unroll
    for (int o = 16; o > 0; o >>= 1) {
        s  += __shfl_xor_sync(0xffffffffu, s, o);
        ss += __shfl_xor_sync(0xffffffffu, ss, o);
    }
    int warp = tid >> 5, lane = tid & 31;
    if (lane == 0) { red[0][warp] = s; red[1][warp] = ss; }
    __syncthreads();
    s  = red[0][0] + red[0][1];
    ss = red[1][0] + red[1][1];
    float mean = s * (1.0f / DIM);
    float var  = ss * (1.0f / DIM) - mean * mean;
    float rstd = rsqrtf(var + 1e-5f);

    // grid knots identical for every feature (broadcast) -> read row 0 only
    float gg[GN];
    #pragma unroll
    for (int i = 0; i < GN; i++) gg[i] = __ldg(grid + i);

    int d0 = tid * 8;
    const float4* lwv = reinterpret_cast<const float4*>(ln_w + d0);
    const float4* lbv = reinterpret_cast<const float4*>(ln_b + d0);
    float4 w0 = lwv[0], w1 = lwv[1], b0v = lbv[0], b1v = lbv[1];
    float lw[8] = {w0.x, w0.y, w0.z, w0.w, w1.x, w1.y, w1.z, w1.w};
    float lb[8] = {b0v.x, b0v.y, b0v.z, b0v.w, b1v.x, b1v.y, b1v.z, b1v.w};

    __half sil[8];
    __half bas[48];

    #pragma unroll
    for (int j = 0; j < 8; j++) {
        float xn = (xs[j] - mean) * rstd * lw[j] + lb[j];
        float sl = xn / (1.0f + expf(-xn));
        sil[j] = __float2half_rn(sl);

        float b[GN - 1];
        #pragma unroll
        for (int i = 0; i < GN - 1; i++)
            b[i] = (xn >= gg[i] && xn < gg[i + 1]) ? 1.0f : 0.0f;
        #pragma unroll
        for (int k = 1; k <= 3; k++) {
            #pragma unroll
            for (int i = 0; i < GN - 1 - k; i++) {
                float left  = (xn - gg[i]) / (gg[i + k] - gg[i]);
                float right = (gg[i + k + 1] - xn) / (gg[i + k + 1] - gg[i + 1]);
                b[i] = left * b[i] + right * b[i + 1];
            }
        }
        #pragma unroll
        for (int i = 0; i < NBASE; i++)
            bas[j * NBASE + i] = __float2half_rn(b[i]);
    }

    __half* arow = g_A + (size_t)token * KTOT;
    // silu: 8 halfs = 16B, contiguous across lanes
    *reinterpret_cast<uint4*>(arow + d0) = *reinterpret_cast<uint4*>(sil);
    // bases: 48 halfs = 96B at 16B alignment (1024 + 96*tid bytes)
    uint4* bsrc = reinterpret_cast<uint4*>(bas);
    uint4* bdst = reinterpret_cast<uint4*>(arow + DIM + (size_t)tid * 48);
    #pragma unroll
    for (int i = 0; i < 6; i++) bdst[i] = bsrc[i];
}

// ---------------- kernel 3: fp16 GEMM 128x128, BK=64, 3-stage, 2 CTA/SM -----
__device__ __forceinline__ void load_stage(__half* sm, int stg, const __half* gA,
                                           int n0, int kt, int tid) {
    __half* As = sm + stg * A_HALFS;
    __half* Bs = sm + SM_B_OFF + stg * B_HALFS;
    #pragma unroll
    for (int i = 0; i < 4; i++) {
        int id = tid + i * 256;
        int r = id >> 3, c = id & 7;
        cp_async16(As + r * ASTR + c * 8, gA + (size_t)r * KTOT + kt + c * 8);
    }
    #pragma unroll
    for (int i = 0; i < 4; i++) {
        int id = tid + i * 256;
        int r = id >> 3, c = id & 7;
        cp_async16(Bs + r * BSTR + c * 8, g_W + (size_t)(n0 + r) * KTOT + kt + c * 8);
    }
    CP_COMMIT();
}

__global__ void __launch_bounds__(256, 2) gemm_kernel(float* __restrict__ out,
                                                      const float* __restrict__ bias) {
    extern __shared__ __half sm[];
    int tid = threadIdx.x;
    int lane = tid & 31, warp = tid >> 5;
    int wm = warp >> 2;           // 0..1 -> M rows [wm*64, +64)
    int wn = warp & 3;            // 0..3 -> N cols [wn*32, +32)
    int lr = lane >> 2, lc = lane & 3;

    int n0 = blockIdx.x * BN;     // x fastest (4) -> W / A-tile L2 reuse
    int m0 = blockIdx.y * BM;
    const __half* gA = g_A + (size_t)m0 * KTOT;

    int a_row = (lane & 15);
    int a_koff = (lane >> 4) << 3;
    int b_row = (lane & 7) + ((lane & 16) >> 1);
    int b_koff = lane & 8;

    float acc[4][4][4];
    #pragma unroll
    for (int i = 0; i < 4; i++)
        #pragma unroll
        for (int j = 0; j < 4; j++)
            #pragma unroll
            for (int r = 0; r < 4; r++) acc[i][j][r] = 0.0f;

    load_stage(sm, 0, gA, n0, 0, tid);
    load_stage(sm, 1, gA, n0, BK, tid);

    for (int t = 0; t < NSTG; t++) {
        CP_WAIT1();
        __syncthreads();

        if (t + STAGES - 1 < NSTG)
            load_stage(sm, (t + STAGES - 1) % STAGES, gA, n0, (t + STAGES - 1) * BK, tid);
        else
            CP_COMMIT();

        int stg = t % STAGES;
        const __half* As = sm + stg * A_HALFS;
        const __half* Bs = sm + SM_B_OFF + stg * B_HALFS;

        #pragma unroll
        for (int kk = 0; kk < 4; kk++) {
            int k0 = kk * 16;
            uint32_t af[4][4];
            #pragma unroll
            for (int mt = 0; mt < 4; mt++) {
                int row = wm * 64 + mt * 16 + a_row;
                ldsm_x4(af[mt], As + row * ASTR + k0 + a_koff);
            }
            uint32_t bf[4][2];
            #pragma unroll
            for (int np = 0; np < 2; np++) {
                uint32_t r[4];
                int col = wn * 32 + np * 16 + b_row;
                ldsm_x4(r, Bs + col * BSTR + k0 + b_koff);
                bf[np * 2][0] = r[0]; bf[np * 2][1] = r[1];
                bf[np * 2 + 1][0] = r[2]; bf[np * 2 + 1][1] = r[3];
            }
            #pragma unroll
            for (int mt = 0; mt < 4; mt++)
                #pragma unroll
                for (int nt = 0; nt < 4; nt++)
                    mma_f16(acc[mt][nt], af[mt], bf[nt]);
        }
    }

    // epilogue
    #pragma unroll
    for (int mt = 0; mt < 4; mt++) {
        #pragma unroll
        for (int nt = 0; nt < 4; nt++) {
            int row = m0 + wm * 64 + mt * 16 + lr;
            int col = n0 + wn * 32 + nt * 8 + lc * 2;
            float b0 = __ldg(bias + col), b1 = __ldg(bias + col + 1);
            float2 v0 = make_float2(acc[mt][nt][0] + b0, acc[mt][nt][1] + b1);
            float2 v1 = make_float2(acc[mt][nt][2] + b0, acc[mt][nt][3] + b1);
            *reinterpret_cast<float2*>(out + (size_t)row * NTOT + col) = v0;
            *reinterpret_cast<float2*>(out + (size_t)(row + 8) * NTOT + col) = v1;
        }
    }
}

// ---------------- launch -----------------------------------------------------
extern "C" void kernel_launch(void* const* d_in, const int* in_sizes, int n_in,
                              void* d_out, int out_size) {
    const float* x        = (const float*)d_in[0];
    const float* ln_w     = (const float*)d_in[1];
    const float* ln_b     = (const float*)d_in[2];
    const float* base_w   = (const float*)d_in[3];
    const float* base_b   = (const float*)d_in[4];
    const float* spline_w = (const float*)d_in[5];
    const float* grid     = (const float*)d_in[6];
    float* out = (float*)d_out;

    cudaFuncSetAttribute(gemm_kernel, cudaFuncAttributeMaxDynamicSharedMemorySize, SMEM_BYTES);

    dim3 gw(KTOT / 256, NTOT);
    build_w_kernel<<<gw, 256>>>(base_w, spline_w);
    act_kernel<<<M_TOT, 64>>>(x, ln_w, ln_b, grid);
    dim3 g(NTOT / BN, M_TOT / BM);    // (4, 256)
    gemm_kernel<<<g, 256, SMEM_BYTES>>>(out, base_b);
}